// round 10
// baseline (speedup 1.0000x reference)
#include <cuda_runtime.h>
#include <cuda_fp16.h>
#include <cstdint>
#include <math.h>

#define NN 50000
#define EE 150000
#define NODE_IN 64
#define EDGE_IN 16
#define D 32
#define EH 128
#define STEPS 3

// Scratch (device globals — no allocation APIs allowed)
__device__ __half g_a[(size_t)EE * EH];        // edge hidden (fp16), 38.4 MB
__device__ __half g_WT[1024 * EH];             // We2^T (fp16), 256 KB
__device__ __half g_Wm_h[(size_t)EE * D * D];  // per-edge W^T[o][i] (fp16), 307 MB
__device__ float g_h[NN * D];                  // node state
__device__ float g_agg[NN * D];                // scatter accumulator

// ===========================================================================
// K1 (fused): blocks [0, EB): a_e = relu(edge_attr @ We1 + be1) -> fp16
//             blocks [EB, EB+512): We2^T -> fp16
// ===========================================================================
#define EB ((EE + 1) / 2)
__global__ void k_edge_fused(const float* __restrict__ ea,
                             const float* __restrict__ We1,
                             const float* __restrict__ be1,
                             const float* __restrict__ We2) {
    if (blockIdx.x < EB) {
        int e = blockIdx.x * 2 + (threadIdx.x >> 7);
        int t = threadIdx.x & 127;
        __shared__ float s_ea[2][EDGE_IN];
        if (e < EE && t < EDGE_IN) s_ea[threadIdx.x >> 7][t] = ea[e * EDGE_IN + t];
        __syncthreads();
        if (e >= EE) return;
        const float* se = s_ea[threadIdx.x >> 7];
        float acc = be1[t];
#pragma unroll
        for (int i = 0; i < EDGE_IN; i++)
            acc = fmaf(se[i], We1[i * EH + t], acc);
        g_a[(size_t)e * EH + t] = __float2half_rn(fmaxf(acc, 0.0f));
    } else {
        int n = (blockIdx.x - EB) * 2 + (threadIdx.x >> 7);   // 0..1023
        int k = threadIdx.x & 127;
        g_WT[n * EH + k] = __float2half_rn(We2[(size_t)k * 1024 + n]);
    }
}

// ===========================================================================
// K2: Wm = a [E,128] @ We2 [128,1024] + be2, fp16 mma.sync.
// Output stored TRANSPOSED per edge: g_Wm_h[e*1024 + o*32 + i], o=c&31, i=c>>5.
// ===========================================================================
#define APITCH 136                         // fp16 elems per smem row
#define TILE_BYTES (128 * APITCH * 2)      // 34816
#define OFF_BIAS 0
#define OFF_A 4096
#define OFF_B0 (OFF_A + TILE_BYTES)
#define OFF_B1 (OFF_B0 + TILE_BYTES)
#define SM_TOTAL (OFF_B1 + TILE_BYTES)     // 108544 -> 2 CTAs/SM

__device__ __forceinline__ uint32_t smem_u32(const void* p) {
    uint32_t a;
    asm("{ .reg .u64 t; cvta.to.shared.u64 t, %1; cvt.u32.u64 %0, t; }" : "=r"(a) : "l"(p));
    return a;
}
__device__ __forceinline__ void mma16816(float* c, const uint32_t* a, const uint32_t* b) {
    asm volatile(
        "mma.sync.aligned.m16n8k16.row.col.f32.f16.f16.f32 "
        "{%0,%1,%2,%3}, {%4,%5,%6,%7}, {%8,%9}, {%0,%1,%2,%3};"
        : "+f"(c[0]), "+f"(c[1]), "+f"(c[2]), "+f"(c[3])
        : "r"(a[0]), "r"(a[1]), "r"(a[2]), "r"(a[3]), "r"(b[0]), "r"(b[1]));
}
__device__ __forceinline__ void ldsm4(uint32_t* r, uint32_t addr) {
    asm volatile("ldmatrix.sync.aligned.m8n8.x4.shared.b16 {%0,%1,%2,%3}, [%4];"
        : "=r"(r[0]), "=r"(r[1]), "=r"(r[2]), "=r"(r[3]) : "r"(addr));
}
__device__ __forceinline__ void cp_async16(uint32_t dst, const void* src) {
    asm volatile("cp.async.cg.shared.global [%0], [%1], 16;" :: "r"(dst), "l"(src));
}

__global__ void __launch_bounds__(256, 2) k_wm_mma(const float* __restrict__ bias) {
    extern __shared__ char smem[];
    uint32_t sbase = smem_u32(smem);
    float* sbias = (float*)(smem + OFF_BIAS);
    int tid = threadIdx.x;
    int wid = tid >> 5;
    int lane = tid & 31;
    int g = lane >> 2;
    int tig = lane & 3;
    int wm = wid >> 2;          // 0..1 (64-row warp tile)
    int wn = wid & 3;           // 0..3 (32-col warp tile)
    int rowBase = blockIdx.x * 128;

    // prefetch B(0)
    for (int idx = tid; idx < 2048; idx += 256) {
        int r = idx >> 4;
        int c = (idx & 15) * 8;
        cp_async16(sbase + OFF_B0 + (uint32_t)((r * APITCH + c) * 2),
                   g_WT + (size_t)r * EH + c);
    }
    asm volatile("cp.async.commit_group;");

    for (int i = tid; i < 1024; i += 256) sbias[i] = bias[i];

    // stage A
    for (int idx = tid; idx < 2048; idx += 256) {
        int r = idx >> 4;
        int c = (idx & 15) * 8;
        int grow = rowBase + r;
        uint4 v = make_uint4(0u, 0u, 0u, 0u);
        if (grow < EE) v = *(const uint4*)(g_a + (size_t)grow * EH + c);
        *(uint4*)(smem + OFF_A + (r * APITCH + c) * 2) = v;
    }

    int a_row = (lane & 7) + ((lane >> 3) & 1) * 8;
    int a_k   = ((lane >> 4) & 1) * 8;
    uint32_t aoff = (uint32_t)(((wm * 64 + a_row) * APITCH + a_k) * 2);
    int b_n = (lane & 7) + ((lane >> 4) & 1) * 8;
    int b_k = ((lane >> 3) & 1) * 8;
    uint32_t boff = (uint32_t)(((wn * 32 + b_n) * APITCH + b_k) * 2);

    for (int nt = 0; nt < 8; nt++) {
        uint32_t curB = (nt & 1) ? OFF_B1 : OFF_B0;
        uint32_t nxtB = (nt & 1) ? OFF_B0 : OFF_B1;

        asm volatile("cp.async.wait_group 0;");
        __syncthreads();

        if (nt < 7) {
            int nBase = (nt + 1) * 128;
            for (int idx = tid; idx < 2048; idx += 256) {
                int r = idx >> 4;
                int c = (idx & 15) * 8;
                cp_async16(sbase + nxtB + (uint32_t)((r * APITCH + c) * 2),
                           g_WT + (size_t)(nBase + r) * EH + c);
            }
            asm volatile("cp.async.commit_group;");
        }

        float acc[4][4][4];
#pragma unroll
        for (int mi = 0; mi < 4; mi++)
#pragma unroll
            for (int ni = 0; ni < 4; ni++)
#pragma unroll
                for (int q = 0; q < 4; q++) acc[mi][ni][q] = 0.0f;

#pragma unroll
        for (int ks = 0; ks < 8; ks++) {
            uint32_t kb = (uint32_t)(ks * 32);
            uint32_t af[4][4], bf[4][2];
#pragma unroll
            for (int mi = 0; mi < 4; mi++)
                ldsm4(af[mi], sbase + OFF_A + aoff + (uint32_t)(mi * 16 * APITCH * 2) + kb);
#pragma unroll
            for (int nj = 0; nj < 2; nj++) {
                uint32_t tb[4];
                ldsm4(tb, sbase + curB + boff + (uint32_t)(nj * 16 * APITCH * 2) + kb);
                bf[nj * 2][0] = tb[0]; bf[nj * 2][1] = tb[1];
                bf[nj * 2 + 1][0] = tb[2]; bf[nj * 2 + 1][1] = tb[3];
            }
#pragma unroll
            for (int mi = 0; mi < 4; mi++)
#pragma unroll
                for (int ni = 0; ni < 4; ni++)
                    mma16816(acc[mi][ni], af[mi], bf[ni]);
        }

        // ---- epilogue: +bias, cvt fp16, TRANSPOSED store W^T[o][i] ----
        int nBase = nt * 128;
#pragma unroll
        for (int mi = 0; mi < 4; mi++) {
            int row0 = rowBase + wm * 64 + mi * 16 + g;
#pragma unroll
            for (int ni = 0; ni < 4; ni++) {
                int col = nBase + wn * 32 + ni * 8 + tig * 2;
                int o0 = col & 31;          // col%32 <= 30, so o0+1 stays in row
                int i0 = col >> 5;
                float b0 = sbias[col], b1 = sbias[col + 1];
                if (row0 < EE) {
                    size_t base = (size_t)row0 * 1024 + (size_t)i0;
                    g_Wm_h[base + o0 * 32]       = __float2half_rn(acc[mi][ni][0] + b0);
                    g_Wm_h[base + (o0 + 1) * 32] = __float2half_rn(acc[mi][ni][1] + b1);
                }
                if (row0 + 8 < EE) {
                    size_t base = (size_t)(row0 + 8) * 1024 + (size_t)i0;
                    g_Wm_h[base + o0 * 32]       = __float2half_rn(acc[mi][ni][2] + b0);
                    g_Wm_h[base + (o0 + 1) * 32] = __float2half_rn(acc[mi][ni][3] + b1);
                }
            }
        }
    }
}

// ===========================================================================
// K3: h = relu(x @ Wn + bn); zero g_agg
// ===========================================================================
__global__ void k_node_init(const float* __restrict__ x,
                            const float* __restrict__ Wn,
                            const float* __restrict__ bn) {
    int warp = (blockIdx.x * blockDim.x + threadIdx.x) >> 5;
    int lane = threadIdx.x & 31;
    if (warp >= NN) return;
    float x0 = x[warp * NODE_IN + lane];
    float x1 = x[warp * NODE_IN + 32 + lane];
    float acc = bn[lane];
#pragma unroll
    for (int i = 0; i < 32; i++) {
        acc = fmaf(__shfl_sync(0xffffffffu, x0, i), Wn[i * D + lane], acc);
        acc = fmaf(__shfl_sync(0xffffffffu, x1, i), Wn[(i + 32) * D + lane], acc);
    }
    g_h[warp * D + lane] = fmaxf(acc, 0.0f);
    g_agg[warp * D + lane] = 0.0f;
}

// ===========================================================================
// K5: per-edge m_o = sum_i h_i * W^T[o][i]; vectorized column loads.
// ===========================================================================
__global__ void k_message(const int* __restrict__ src, const int* __restrict__ dst) {
    int warp = (blockIdx.x * blockDim.x + threadIdx.x) >> 5;
    int lane = threadIdx.x & 31;
    if (warp >= EE) return;
    int s = src[warp];
    int d = dst[warp];
    float hv = g_h[s * D + lane];
    const uint4* W = (const uint4*)(g_Wm_h + (size_t)warp * 1024 + lane * 32);
    uint4 w0 = __ldg(W), w1 = __ldg(W + 1), w2 = __ldg(W + 2), w3 = __ldg(W + 3);
    float m = 0.0f;
    uint4 wv[4] = {w0, w1, w2, w3};
#pragma unroll
    for (int j = 0; j < 4; j++) {
        const __half2* p = (const __half2*)&wv[j];
#pragma unroll
        for (int q = 0; q < 4; q++) {
            float2 f = __half22float2(p[q]);
            int i = j * 8 + q * 2;
            m = fmaf(__shfl_sync(0xffffffffu, hv, i), f.x, m);
            m = fmaf(__shfl_sync(0xffffffffu, hv, i + 1), f.y, m);
        }
    }
    atomicAdd(g_agg + d * D + lane, m);
}

// ===========================================================================
// K6: conv = relu(agg + h@Wroot + bconv); GRU(conv, h); re-zero agg
// ===========================================================================
__global__ void __launch_bounds__(256) k_gru(const float* __restrict__ Wroot,
                                             const float* __restrict__ bconv,
                                             const float* __restrict__ Wih,
                                             const float* __restrict__ Whh,
                                             const float* __restrict__ bih,
                                             const float* __restrict__ bhh,
                                             float* __restrict__ out_ext,
                                             int use_ext) {
    __shared__ float sWihT[32 * 96];
    __shared__ float sWhhT[32 * 96];
    __shared__ float sWroot[32 * 32];
    int t = threadIdx.x;
    for (int idx = t; idx < 96 * 32; idx += blockDim.x) {
        int i = idx / 96, gg = idx % 96;
        sWihT[idx] = Wih[gg * 32 + i];
        sWhhT[idx] = Whh[gg * 32 + i];
    }
    for (int idx = t; idx < 32 * 32; idx += blockDim.x)
        sWroot[idx] = Wroot[idx];
    __syncthreads();

    int warp = (blockIdx.x * blockDim.x + t) >> 5;
    int lane = t & 31;
    if (warp >= NN) return;

    float hv = g_h[warp * D + lane];
    float c = g_agg[warp * D + lane] + bconv[lane];
    g_agg[warp * D + lane] = 0.0f;
#pragma unroll
    for (int i = 0; i < 32; i++)
        c = fmaf(__shfl_sync(0xffffffffu, hv, i), sWroot[i * D + lane], c);
    c = fmaxf(c, 0.0f);

    float gr = bih[lane], gz = bih[32 + lane], gn = bih[64 + lane];
    float hr = bhh[lane], hz = bhh[32 + lane], hn = bhh[64 + lane];
#pragma unroll
    for (int i = 0; i < 32; i++) {
        float cv  = __shfl_sync(0xffffffffu, c, i);
        float hvi = __shfl_sync(0xffffffffu, hv, i);
        const float* wi = sWihT + i * 96;
        const float* wh = sWhhT + i * 96;
        gr = fmaf(cv, wi[lane], gr);
        gz = fmaf(cv, wi[32 + lane], gz);
        gn = fmaf(cv, wi[64 + lane], gn);
        hr = fmaf(hvi, wh[lane], hr);
        hz = fmaf(hvi, wh[32 + lane], hz);
        hn = fmaf(hvi, wh[64 + lane], hn);
    }
    float r  = 1.0f / (1.0f + expf(-(gr + hr)));
    float z  = 1.0f / (1.0f + expf(-(gz + hz)));
    float nn = tanhf(gn + r * hn);
    float hnew = (1.0f - z) * nn + z * hv;

    if (use_ext) out_ext[warp * D + lane] = hnew;
    else         g_h[warp * D + lane] = hnew;
}

// ===========================================================================
extern "C" void kernel_launch(void* const* d_in, const int* in_sizes, int n_in,
                              void* d_out, int out_size) {
    const float* x     = (const float*)d_in[0];
    const int*   ei    = (const int*)d_in[1];
    const float* ea    = (const float*)d_in[2];
    const float* Wn    = (const float*)d_in[3];
    const float* bn    = (const float*)d_in[4];
    const float* We1   = (const float*)d_in[5];
    const float* be1   = (const float*)d_in[6];
    const float* We2   = (const float*)d_in[7];
    const float* be2   = (const float*)d_in[8];
    const float* Wroot = (const float*)d_in[9];
    const float* bconv = (const float*)d_in[10];
    const float* Wih   = (const float*)d_in[11];
    const float* Whh   = (const float*)d_in[12];
    const float* bih   = (const float*)d_in[13];
    const float* bhh   = (const float*)d_in[14];
    const int* src = ei;
    const int* dst = ei + EE;
    float* out = (float*)d_out;

    cudaFuncSetAttribute(k_wm_mma, cudaFuncAttributeMaxDynamicSharedMemorySize, SM_TOTAL);

    // order chosen so first k_message lands in the ncu capture slot (#4)
    k_node_init<<<(NN * 32 + 255) / 256, 256>>>(x, Wn, bn);
    k_edge_fused<<<EB + 512, 256>>>(ea, We1, be1, We2);
    int mtiles = (EE + 127) / 128;   // 1172
    k_wm_mma<<<mtiles, 256, SM_TOTAL>>>(be2);

    for (int s = 0; s < STEPS; s++) {
        k_message<<<(EE * 32 + 255) / 256, 256>>>(src, dst);
        int last = (s == STEPS - 1) ? 1 : 0;
        k_gru<<<(NN * 32 + 255) / 256, 256>>>(Wroot, bconv, Wih, Whh, bih, bhh,
                                              out, last);
    }
}

// round 11
// speedup vs baseline: 3.1121x; 3.1121x over previous
#include <cuda_runtime.h>
#include <cuda_fp16.h>
#include <cstdint>
#include <math.h>

#define NN 50000
#define EE 150000
#define NODE_IN 64
#define EDGE_IN 16
#define D 32
#define EH 128
#define STEPS 3

// Scratch (device globals — no allocation APIs allowed)
__device__ __half g_a[(size_t)EE * EH];        // edge hidden (fp16), 38.4 MB
__device__ __half g_WT[1024 * EH];             // We2^T (fp16), 256 KB
__device__ __half g_Wm_h[(size_t)EE * D * D];  // per-edge matrices (fp16), 307 MB
__device__ float g_h[NN * D];                  // node state
__device__ float g_agg[NN * D];                // scatter accumulator
__device__ float g_WihT[96 * 32];              // Wih^T [32][96]
__device__ float g_WhhT[96 * 32];              // Whh^T [32][96]

// ===========================================================================
// K0: one-off transpose of GRU weights (tiny)
// ===========================================================================
__global__ void k_prep(const float* __restrict__ Wih, const float* __restrict__ Whh) {
    int t = threadIdx.x;
    for (int idx = t; idx < 96 * 32; idx += 256) {
        int i = idx / 96, gg = idx % 96;     // dst contiguous
        g_WihT[idx] = Wih[gg * 32 + i];
        g_WhhT[idx] = Whh[gg * 32 + i];
    }
}

// ===========================================================================
// K1 (fused): blocks [0, EB): a_e = relu(edge_attr @ We1 + be1) -> fp16
//             blocks [EB, EB+512): We2^T -> fp16
// ===========================================================================
#define EB ((EE + 1) / 2)
__global__ void k_edge_fused(const float* __restrict__ ea,
                             const float* __restrict__ We1,
                             const float* __restrict__ be1,
                             const float* __restrict__ We2) {
    if (blockIdx.x < EB) {
        int e = blockIdx.x * 2 + (threadIdx.x >> 7);
        int t = threadIdx.x & 127;
        __shared__ float s_ea[2][EDGE_IN];
        if (e < EE && t < EDGE_IN) s_ea[threadIdx.x >> 7][t] = ea[e * EDGE_IN + t];
        __syncthreads();
        if (e >= EE) return;
        const float* se = s_ea[threadIdx.x >> 7];
        float acc = be1[t];
#pragma unroll
        for (int i = 0; i < EDGE_IN; i++)
            acc = fmaf(se[i], We1[i * EH + t], acc);
        g_a[(size_t)e * EH + t] = __float2half_rn(fmaxf(acc, 0.0f));
    } else {
        int n = (blockIdx.x - EB) * 2 + (threadIdx.x >> 7);   // 0..1023
        int k = threadIdx.x & 127;
        g_WT[n * EH + k] = __float2half_rn(We2[(size_t)k * 1024 + n]);
    }
}

// ===========================================================================
// K2: Wm = a [E,128] @ We2 [128,1024] + be2, fp16 mma.sync.
// Coalesced __half2 output (row-major per edge). cp.async double-buffered B.
// ===========================================================================
#define APITCH 136
#define TILE_BYTES (128 * APITCH * 2)
#define OFF_BIAS 0
#define OFF_A 4096
#define OFF_B0 (OFF_A + TILE_BYTES)
#define OFF_B1 (OFF_B0 + TILE_BYTES)
#define SM_TOTAL (OFF_B1 + TILE_BYTES)     // 108544 -> 2 CTAs/SM

__device__ __forceinline__ uint32_t smem_u32(const void* p) {
    uint32_t a;
    asm("{ .reg .u64 t; cvta.to.shared.u64 t, %1; cvt.u32.u64 %0, t; }" : "=r"(a) : "l"(p));
    return a;
}
__device__ __forceinline__ void mma16816(float* c, const uint32_t* a, const uint32_t* b) {
    asm volatile(
        "mma.sync.aligned.m16n8k16.row.col.f32.f16.f16.f32 "
        "{%0,%1,%2,%3}, {%4,%5,%6,%7}, {%8,%9}, {%0,%1,%2,%3};"
        : "+f"(c[0]), "+f"(c[1]), "+f"(c[2]), "+f"(c[3])
        : "r"(a[0]), "r"(a[1]), "r"(a[2]), "r"(a[3]), "r"(b[0]), "r"(b[1]));
}
__device__ __forceinline__ void ldsm4(uint32_t* r, uint32_t addr) {
    asm volatile("ldmatrix.sync.aligned.m8n8.x4.shared.b16 {%0,%1,%2,%3}, [%4];"
        : "=r"(r[0]), "=r"(r[1]), "=r"(r[2]), "=r"(r[3]) : "r"(addr));
}
__device__ __forceinline__ void cp_async16(uint32_t dst, const void* src) {
    asm volatile("cp.async.cg.shared.global [%0], [%1], 16;" :: "r"(dst), "l"(src));
}

__global__ void __launch_bounds__(256, 2) k_wm_mma(const float* __restrict__ bias) {
    extern __shared__ char smem[];
    uint32_t sbase = smem_u32(smem);
    float* sbias = (float*)(smem + OFF_BIAS);
    int tid = threadIdx.x;
    int wid = tid >> 5;
    int lane = tid & 31;
    int g = lane >> 2;
    int tig = lane & 3;
    int wm = wid >> 2;          // 0..1 (64-row warp tile)
    int wn = wid & 3;           // 0..3 (32-col warp tile)
    int rowBase = blockIdx.x * 128;

    // prefetch B(0)
    for (int idx = tid; idx < 2048; idx += 256) {
        int r = idx >> 4;
        int c = (idx & 15) * 8;
        cp_async16(sbase + OFF_B0 + (uint32_t)((r * APITCH + c) * 2),
                   g_WT + (size_t)r * EH + c);
    }
    asm volatile("cp.async.commit_group;");

    for (int i = tid; i < 1024; i += 256) sbias[i] = bias[i];

    // stage A
    for (int idx = tid; idx < 2048; idx += 256) {
        int r = idx >> 4;
        int c = (idx & 15) * 8;
        int grow = rowBase + r;
        uint4 v = make_uint4(0u, 0u, 0u, 0u);
        if (grow < EE) v = *(const uint4*)(g_a + (size_t)grow * EH + c);
        *(uint4*)(smem + OFF_A + (r * APITCH + c) * 2) = v;
    }

    int a_row = (lane & 7) + ((lane >> 3) & 1) * 8;
    int a_k   = ((lane >> 4) & 1) * 8;
    uint32_t aoff = (uint32_t)(((wm * 64 + a_row) * APITCH + a_k) * 2);
    int b_n = (lane & 7) + ((lane >> 4) & 1) * 8;
    int b_k = ((lane >> 3) & 1) * 8;
    uint32_t boff = (uint32_t)(((wn * 32 + b_n) * APITCH + b_k) * 2);

    for (int nt = 0; nt < 8; nt++) {
        uint32_t curB = (nt & 1) ? OFF_B1 : OFF_B0;
        uint32_t nxtB = (nt & 1) ? OFF_B0 : OFF_B1;

        asm volatile("cp.async.wait_group 0;");
        __syncthreads();

        if (nt < 7) {
            int nBase = (nt + 1) * 128;
            for (int idx = tid; idx < 2048; idx += 256) {
                int r = idx >> 4;
                int c = (idx & 15) * 8;
                cp_async16(sbase + nxtB + (uint32_t)((r * APITCH + c) * 2),
                           g_WT + (size_t)(nBase + r) * EH + c);
            }
            asm volatile("cp.async.commit_group;");
        }

        float acc[4][4][4];
#pragma unroll
        for (int mi = 0; mi < 4; mi++)
#pragma unroll
            for (int ni = 0; ni < 4; ni++)
#pragma unroll
                for (int q = 0; q < 4; q++) acc[mi][ni][q] = 0.0f;

#pragma unroll
        for (int ks = 0; ks < 8; ks++) {
            uint32_t kb = (uint32_t)(ks * 32);
            uint32_t af[4][4], bf[4][2];
#pragma unroll
            for (int mi = 0; mi < 4; mi++)
                ldsm4(af[mi], sbase + OFF_A + aoff + (uint32_t)(mi * 16 * APITCH * 2) + kb);
#pragma unroll
            for (int nj = 0; nj < 2; nj++) {
                uint32_t tb[4];
                ldsm4(tb, sbase + curB + boff + (uint32_t)(nj * 16 * APITCH * 2) + kb);
                bf[nj * 2][0] = tb[0]; bf[nj * 2][1] = tb[1];
                bf[nj * 2 + 1][0] = tb[2]; bf[nj * 2 + 1][1] = tb[3];
            }
#pragma unroll
            for (int mi = 0; mi < 4; mi++)
#pragma unroll
                for (int ni = 0; ni < 4; ni++)
                    mma16816(acc[mi][ni], af[mi], bf[ni]);
        }

        // ---- epilogue: +bias, cvt fp16, coalesced __half2 store ----
        int nBase = nt * 128;
#pragma unroll
        for (int mi = 0; mi < 4; mi++) {
            int row0 = rowBase + wm * 64 + mi * 16 + g;
#pragma unroll
            for (int ni = 0; ni < 4; ni++) {
                int col = nBase + wn * 32 + ni * 8 + tig * 2;
                float b0 = sbias[col], b1 = sbias[col + 1];
                if (row0 < EE) {
                    __half2 v = __floats2half2_rn(acc[mi][ni][0] + b0, acc[mi][ni][1] + b1);
                    *(__half2*)(g_Wm_h + (size_t)row0 * 1024 + col) = v;
                }
                if (row0 + 8 < EE) {
                    __half2 v = __floats2half2_rn(acc[mi][ni][2] + b0, acc[mi][ni][3] + b1);
                    *(__half2*)(g_Wm_h + (size_t)(row0 + 8) * 1024 + col) = v;
                }
            }
        }
    }
}

// ===========================================================================
// K3: h = relu(x @ Wn + bn); zero g_agg
// ===========================================================================
__global__ void k_node_init(const float* __restrict__ x,
                            const float* __restrict__ Wn,
                            const float* __restrict__ bn) {
    int warp = (blockIdx.x * blockDim.x + threadIdx.x) >> 5;
    int lane = threadIdx.x & 31;
    if (warp >= NN) return;
    float x0 = x[warp * NODE_IN + lane];
    float x1 = x[warp * NODE_IN + 32 + lane];
    float acc = bn[lane];
#pragma unroll
    for (int i = 0; i < 32; i++) {
        acc = fmaf(__shfl_sync(0xffffffffu, x0, i), Wn[i * D + lane], acc);
        acc = fmaf(__shfl_sync(0xffffffffu, x1, i), Wn[(i + 32) * D + lane], acc);
    }
    g_h[warp * D + lane] = fmaxf(acc, 0.0f);
    g_agg[warp * D + lane] = 0.0f;
}

// ===========================================================================
// K5: per-edge m = h[src]^T Wm_e (fp16, row-major) ; atomicAdd into g_agg[dst]
// ===========================================================================
__global__ void k_message(const int* __restrict__ src, const int* __restrict__ dst) {
    int warp = (blockIdx.x * blockDim.x + threadIdx.x) >> 5;
    int lane = threadIdx.x & 31;
    if (warp >= EE) return;
    int s = src[warp];
    int d = dst[warp];
    float hv = g_h[s * D + lane];
    const __half* W = g_Wm_h + (size_t)warp * 1024;
    float m = 0.0f;
#pragma unroll
    for (int i = 0; i < 32; i++)
        m = fmaf(__shfl_sync(0xffffffffu, hv, i), __half2float(__ldg(W + i * D + lane)), m);
    atomicAdd(g_agg + d * D + lane, m);
}

// ===========================================================================
// K6: conv = relu(agg + h@Wroot + bconv); GRU(conv, h); re-zero agg.
// Persistent grid-stride blocks; weights staged coalesced from pre-transposed
// globals (float4 LDG -> contiguous STS, no conflicts, no scatter).
// ===========================================================================
#define GRU_BLOCKS 1184
__global__ void __launch_bounds__(256) k_gru(const float* __restrict__ Wroot,
                                             const float* __restrict__ bconv,
                                             const float* __restrict__ bih,
                                             const float* __restrict__ bhh,
                                             float* __restrict__ out_ext,
                                             int use_ext) {
    __shared__ float sWihT[96 * 32];
    __shared__ float sWhhT[96 * 32];
    __shared__ float sWroot[32 * 32];
    int t = threadIdx.x;
    {
        const float4* a = (const float4*)g_WihT;
        const float4* b = (const float4*)g_WhhT;
        float4* sa = (float4*)sWihT;
        float4* sb = (float4*)sWhhT;
        for (int idx = t; idx < 768; idx += 256) { sa[idx] = a[idx]; sb[idx] = b[idx]; }
        const float4* wr = (const float4*)Wroot;
        float4* sr = (float4*)sWroot;
        if (t < 256) sr[t] = wr[t];
    }
    __syncthreads();

    int lane = t & 31;
    int wlocal = t >> 5;
    // per-lane biases hoisted out of the node loop
    float bc  = bconv[lane];
    float b_ir = bih[lane], b_iz = bih[32 + lane], b_in = bih[64 + lane];
    float b_hr = bhh[lane], b_hz = bhh[32 + lane], b_hn = bhh[64 + lane];

    int totalWarps = GRU_BLOCKS * 8;
    for (int node = blockIdx.x * 8 + wlocal; node < NN; node += totalWarps) {
        float hv = g_h[node * D + lane];
        float c = g_agg[node * D + lane] + bc;
        g_agg[node * D + lane] = 0.0f;
#pragma unroll
        for (int i = 0; i < 32; i++)
            c = fmaf(__shfl_sync(0xffffffffu, hv, i), sWroot[i * D + lane], c);
        c = fmaxf(c, 0.0f);

        float gr = b_ir, gz = b_iz, gn = b_in;
        float hr = b_hr, hz = b_hz, hn = b_hn;
#pragma unroll
        for (int i = 0; i < 32; i++) {
            float cv  = __shfl_sync(0xffffffffu, c, i);
            float hvi = __shfl_sync(0xffffffffu, hv, i);
            const float* wi = sWihT + i * 96;
            const float* wh = sWhhT + i * 96;
            gr = fmaf(cv, wi[lane], gr);
            gz = fmaf(cv, wi[32 + lane], gz);
            gn = fmaf(cv, wi[64 + lane], gn);
            hr = fmaf(hvi, wh[lane], hr);
            hz = fmaf(hvi, wh[32 + lane], hz);
            hn = fmaf(hvi, wh[64 + lane], hn);
        }
        float r  = 1.0f / (1.0f + expf(-(gr + hr)));
        float z  = 1.0f / (1.0f + expf(-(gz + hz)));
        float nn = tanhf(gn + r * hn);
        float hnew = (1.0f - z) * nn + z * hv;

        if (use_ext) out_ext[node * D + lane] = hnew;
        else         g_h[node * D + lane] = hnew;
    }
}

// ===========================================================================
extern "C" void kernel_launch(void* const* d_in, const int* in_sizes, int n_in,
                              void* d_out, int out_size) {
    const float* x     = (const float*)d_in[0];
    const int*   ei    = (const int*)d_in[1];
    const float* ea    = (const float*)d_in[2];
    const float* Wn    = (const float*)d_in[3];
    const float* bn    = (const float*)d_in[4];
    const float* We1   = (const float*)d_in[5];
    const float* be1   = (const float*)d_in[6];
    const float* We2   = (const float*)d_in[7];
    const float* be2   = (const float*)d_in[8];
    const float* Wroot = (const float*)d_in[9];
    const float* bconv = (const float*)d_in[10];
    const float* Wih   = (const float*)d_in[11];
    const float* Whh   = (const float*)d_in[12];
    const float* bih   = (const float*)d_in[13];
    const float* bhh   = (const float*)d_in[14];
    const int* src = ei;
    const int* dst = ei + EE;
    float* out = (float*)d_out;

    cudaFuncSetAttribute(k_wm_mma, cudaFuncAttributeMaxDynamicSharedMemorySize, SM_TOTAL);

    // order chosen so k_wm_mma is launch #4 (ncu capture slot)
    k_node_init<<<(NN * 32 + 255) / 256, 256>>>(x, Wn, bn);
    k_prep<<<1, 256>>>(Wih, Whh);
    k_edge_fused<<<EB + 512, 256>>>(ea, We1, be1, We2);
    int mtiles = (EE + 127) / 128;   // 1172
    k_wm_mma<<<mtiles, 256, SM_TOTAL>>>(be2);

    for (int s = 0; s < STEPS; s++) {
        k_message<<<(EE * 32 + 255) / 256, 256>>>(src, dst);
        int last = (s == STEPS - 1) ? 1 : 0;
        k_gru<<<GRU_BLOCKS, 256>>>(Wroot, bconv, bih, bhh, out, last);
    }
}